// round 1
// baseline (speedup 1.0000x reference)
#include <cuda_runtime.h>
#include <cuda_bf16.h>

// Problem shape (fixed by the reference):
//   x      [B*S=16384, 1024]  f32
//   W_qkv  [1024, 3072]       f32
//   b_qkv  [3072]             f32
//   out    [16384, 16, 64]    f32   (contiguous 1024 floats per token)
#define M_ 16384
#define N_ 3072
#define K_ 1024

// Scratch for the qkv projection (192 MB). __device__ global = allowed scratch.
__device__ float g_qkv[(size_t)M_ * (size_t)N_];

// ---------------------------------------------------------------------------
// Kernel 1: qkv = x @ W + b   (fp32 SIMT SGEMM, 128x128 block tile, 8x8/thread)
// ---------------------------------------------------------------------------
__global__ __launch_bounds__(256, 1) void sgemm_qkv_kernel(
    const float* __restrict__ X,
    const float* __restrict__ W,
    const float* __restrict__ bias)
{
    __shared__ float As[16][128];   // A tile stored transposed: As[k][m]
    __shared__ float Bs[16][128];   // B tile: Bs[k][n]

    const int tid = threadIdx.x;
    const int tx  = tid & 15;       // 16 threads across N
    const int ty  = tid >> 4;       // 16 threads across M
    const int bx  = blockIdx.x;     // N tile index (24)
    const int by  = blockIdx.y;     // M tile index (128)

    const float* Xb = X + (size_t)by * 128 * K_;
    const float* Wb = W + bx * 128;

    float acc[8][8];
    #pragma unroll
    for (int i = 0; i < 8; i++)
        #pragma unroll
        for (int j = 0; j < 8; j++) acc[i][j] = 0.0f;

    for (int k0 = 0; k0 < K_; k0 += 16) {
        // Load A tile: 128 rows x 16 cols = 512 float4, 2 per thread.
        #pragma unroll
        for (int r = 0; r < 2; r++) {
            int i = tid + r * 256;
            int arow = i >> 2;            // 0..127
            int acol = (i & 3) << 2;      // 0,4,8,12
            float4 v = *(const float4*)(Xb + (size_t)arow * K_ + k0 + acol);
            As[acol + 0][arow] = v.x;
            As[acol + 1][arow] = v.y;
            As[acol + 2][arow] = v.z;
            As[acol + 3][arow] = v.w;
        }
        // Load B tile: 16 rows x 128 cols = 512 float4, 2 per thread.
        #pragma unroll
        for (int r = 0; r < 2; r++) {
            int i = tid + r * 256;
            int brow = i >> 5;            // 0..15
            int bcol = (i & 31) << 2;     // 0..124
            *(float4*)&Bs[brow][bcol] =
                *(const float4*)(Wb + (size_t)(k0 + brow) * N_ + bcol);
        }
        __syncthreads();

        #pragma unroll
        for (int k = 0; k < 16; k++) {
            float ra[8], rb[8];
            #pragma unroll
            for (int i = 0; i < 8; i++) ra[i] = As[k][ty * 8 + i];
            #pragma unroll
            for (int j = 0; j < 8; j++) rb[j] = Bs[k][tx * 8 + j];
            #pragma unroll
            for (int i = 0; i < 8; i++)
                #pragma unroll
                for (int j = 0; j < 8; j++)
                    acc[i][j] = fmaf(ra[i], rb[j], acc[i][j]);
        }
        __syncthreads();
    }

    // Epilogue: add bias, write 8x8 tile with float4 stores.
    const int row0 = by * 128 + ty * 8;
    const int col0 = bx * 128 + tx * 8;
    float bv[8];
    #pragma unroll
    for (int j = 0; j < 8; j++) bv[j] = bias[col0 + j];
    #pragma unroll
    for (int i = 0; i < 8; i++) {
        float4 o0 = make_float4(acc[i][0] + bv[0], acc[i][1] + bv[1],
                                acc[i][2] + bv[2], acc[i][3] + bv[3]);
        float4 o1 = make_float4(acc[i][4] + bv[4], acc[i][5] + bv[5],
                                acc[i][6] + bv[6], acc[i][7] + bv[7]);
        float* dst = &g_qkv[(size_t)(row0 + i) * N_ + col0];
        *(float4*)dst       = o0;
        *(float4*)(dst + 4) = o1;
    }
}

// ---------------------------------------------------------------------------
// Kernel 2: per-token windowed attention.
// One block per token (16384 blocks, 256 threads).
// Layout per token row (3072 floats): head h -> Q at [h*192, +64),
// K at [h*192+64, +64), V at [h*192+128, +64).
// ---------------------------------------------------------------------------
__global__ __launch_bounds__(256, 4) void attn_kernel(float* __restrict__ out)
{
    __shared__ __align__(16) float qkv[3072];
    __shared__ float E[256];       // exp-masked scores, E[h*16+g]
    __shared__ float invden[16];

    const int token = blockIdx.x;
    const int tid   = threadIdx.x;

    // Stage the whole token row into smem (768 float4).
    const float* row = g_qkv + (size_t)token * N_;
    #pragma unroll
    for (int r = 0; r < 3; r++) {
        int i = tid + r * 256;
        ((float4*)qkv)[i] = ((const float4*)row)[i];
    }
    __syncthreads();

    // Scores: one (h,g) per thread. Skew d by tid to avoid the 16-way
    // bank conflict from the stride-192 (== 0 mod 32 banks) K rows.
    const int h = tid >> 4;
    const int g = tid & 15;
    const float* qp = &qkv[h * 192];
    const float* kp = &qkv[g * 192 + 64];
    float s = 0.0f;
    #pragma unroll
    for (int dd = 0; dd < 64; dd++) {
        int d = (dd + tid) & 63;
        s = fmaf(qp[d], kp[d], s);
    }
    s -= 20.0f;                                      // s = QK - UMV
    E[tid] = (s > 20.0f || s < -20.0f) ? 0.0f : expf(s);
    __syncthreads();

    if (tid < 16) {
        float den = 0.0f;
        #pragma unroll
        for (int gg = 0; gg < 16; gg++) den += E[tid * 16 + gg];
        invden[tid] = 1.0f / den;
    }
    __syncthreads();

    // out[h,d] = (1/den_h) * sum_g E[h,g] * V[g,d]; 4 outputs per thread,
    // contiguous writes.
    float* o = out + (size_t)token * 1024;
    #pragma unroll
    for (int r = 0; r < 4; r++) {
        int idx = tid + r * 256;
        int hh = idx >> 6;
        int d  = idx & 63;
        float a = 0.0f;
        #pragma unroll
        for (int gg = 0; gg < 16; gg++)
            a = fmaf(E[hh * 16 + gg], qkv[gg * 192 + 128 + d], a);
        o[idx] = a * invden[hh];
    }
}

// ---------------------------------------------------------------------------
extern "C" void kernel_launch(void* const* d_in, const int* in_sizes, int n_in,
                              void* d_out, int out_size)
{
    const float* x = (const float*)d_in[0];
    const float* W = (const float*)d_in[1];
    const float* b = (const float*)d_in[2];
    float* out = (float*)d_out;

    dim3 grid_gemm(N_ / 128, M_ / 128);   // (24, 128)
    sgemm_qkv_kernel<<<grid_gemm, 256>>>(x, W, b);
    attn_kernel<<<M_, 256>>>(out);
}

// round 4
// speedup vs baseline: 2.3177x; 2.3177x over previous
#include <cuda_runtime.h>
#include <cuda_bf16.h>
#include <cstdint>

#define M_ 16384
#define N_ 3072
#define K_ 1024

// -------- device scratch (allowed: __device__ globals) --------
__device__ float g_qkv[(size_t)M_ * N_];               // 192 MB
__device__ __nv_bfloat16 g_Ah[(size_t)M_ * K_];        // 32 MB  x hi   [M,K]
__device__ __nv_bfloat16 g_Al[(size_t)M_ * K_];        // 32 MB  x lo   [M,K]
__device__ __nv_bfloat16 g_Bh[(size_t)N_ * K_];        // 6 MB   W^T hi [N,K]
__device__ __nv_bfloat16 g_Bl[(size_t)N_ * K_];        // 6 MB   W^T lo [N,K]

// ---------------------------------------------------------------------------
// Pre-kernel 1: split x -> bf16 hi/lo, same [M,K] layout.
// ---------------------------------------------------------------------------
__global__ __launch_bounds__(256) void split_x_kernel(const float* __restrict__ x)
{
    size_t idx = (size_t)blockIdx.x * 256 + threadIdx.x;    // float4 index
    float4 v = ((const float4*)x)[idx];
    __nv_bfloat16 hx = __float2bfloat16(v.x);
    __nv_bfloat16 hy = __float2bfloat16(v.y);
    __nv_bfloat16 hz = __float2bfloat16(v.z);
    __nv_bfloat16 hw = __float2bfloat16(v.w);
    __nv_bfloat16 lx = __float2bfloat16(v.x - __bfloat162float(hx));
    __nv_bfloat16 ly = __float2bfloat16(v.y - __bfloat162float(hy));
    __nv_bfloat16 lz = __float2bfloat16(v.z - __bfloat162float(hz));
    __nv_bfloat16 lw = __float2bfloat16(v.w - __bfloat162float(hw));
    __nv_bfloat162 h01; h01.x = hx; h01.y = hy;
    __nv_bfloat162 h23; h23.x = hz; h23.y = hw;
    __nv_bfloat162 l01; l01.x = lx; l01.y = ly;
    __nv_bfloat162 l23; l23.x = lz; l23.y = lw;
    ((__nv_bfloat162*)g_Ah)[2 * idx]     = h01;
    ((__nv_bfloat162*)g_Ah)[2 * idx + 1] = h23;
    ((__nv_bfloat162*)g_Al)[2 * idx]     = l01;
    ((__nv_bfloat162*)g_Al)[2 * idx + 1] = l23;
}

// ---------------------------------------------------------------------------
// Pre-kernel 2: transpose + split W [K,N] -> g_Bh/g_Bl bf16 [N,K].
// ---------------------------------------------------------------------------
__global__ __launch_bounds__(256) void split_w_kernel(const float* __restrict__ W)
{
    __shared__ float t[32][33];
    const int k0 = blockIdx.x * 32;
    const int n0 = blockIdx.y * 32;
    const int tid = threadIdx.x;
    #pragma unroll
    for (int i = 0; i < 4; i++) {
        int idx = tid + i * 256;
        int r = idx >> 5, c = idx & 31;              // r = k local, c = n local
        t[r][c] = W[(size_t)(k0 + r) * N_ + n0 + c];
    }
    __syncthreads();
    #pragma unroll
    for (int i = 0; i < 4; i++) {
        int idx = tid + i * 256;
        int r = idx >> 5, c = idx & 31;              // r = n local, c = k local
        float v = t[c][r];
        __nv_bfloat16 hi = __float2bfloat16(v);
        __nv_bfloat16 lo = __float2bfloat16(v - __bfloat162float(hi));
        size_t o = (size_t)(n0 + r) * K_ + k0 + c;
        g_Bh[o] = hi;
        g_Bl[o] = lo;
    }
}

// ---------------------------------------------------------------------------
// Main GEMM: qkv = x @ W + b via mma.sync.m16n8k16 bf16, 3-pass split.
// CTA 128x128, 8 warps (2x4), warp tile 64x32, KC=32, cp.async double buffer.
// smem rows padded to 40 bf16 (80B) -> conflict-free ldmatrix.
// ---------------------------------------------------------------------------
#define KC 32
#define ASTRIDE 40
#define ROWB (ASTRIDE * 2)                 // 80 bytes per smem row
#define TILE_BYTES (128 * ROWB)            // 10240
#define STG_BYTES (4 * TILE_BYTES)         // Ah, Al, Bh, Bl
#define SMEM_TOTAL (2 * STG_BYTES)         // 81920

__device__ __forceinline__ uint32_t cvta_smem(const void* p) {
    uint32_t a;
    asm("{ .reg .u64 t; cvta.to.shared.u64 t, %1; cvt.u32.u64 %0, t; }"
        : "=r"(a) : "l"(p));
    return a;
}

#define CP16(dst, src) \
    asm volatile("cp.async.cg.shared.global [%0], [%1], 16;" \
                 :: "r"(dst), "l"(src) : "memory")

#define LDSM4(r, addr) \
    asm volatile("ldmatrix.sync.aligned.m8n8.x4.shared.b16 {%0,%1,%2,%3}, [%4];" \
                 : "=r"((r)[0]), "=r"((r)[1]), "=r"((r)[2]), "=r"((r)[3]) \
                 : "r"(addr))

#define MMA16816(c, a, b0, b1) \
    asm volatile("mma.sync.aligned.m16n8k16.row.col.f32.bf16.bf16.f32 " \
                 "{%0,%1,%2,%3}, {%4,%5,%6,%7}, {%8,%9}, {%0,%1,%2,%3};" \
                 : "+f"((c)[0]), "+f"((c)[1]), "+f"((c)[2]), "+f"((c)[3]) \
                 : "r"((a)[0]), "r"((a)[1]), "r"((a)[2]), "r"((a)[3]), \
                   "r"(b0), "r"(b1))

__global__ __launch_bounds__(256) void gemm_bf16_kernel(const float* __restrict__ bias)
{
    extern __shared__ __align__(128) char smem[];
    const uint32_t sb = cvta_smem(smem);

    const int tid  = threadIdx.x;
    const int wid  = tid >> 5;
    const int lane = tid & 31;
    const int wm   = wid >> 2;          // 0..1 (M)
    const int wn   = wid & 3;           // 0..3 (N)
    const int n0 = blockIdx.x * 128;
    const int m0 = blockIdx.y * 128;

    // per-thread cp.async coordinates: 2 x (row, 16B col) per matrix
    const int r0 = tid >> 2;            // rows 0..63
    const int r1 = r0 + 64;             // rows 64..127
    const int c16 = (tid & 3) * 16;     // byte offset within 64B row payload

    float acc[4][4][4];
    #pragma unroll
    for (int i = 0; i < 4; i++)
        #pragma unroll
        for (int j = 0; j < 4; j++)
            #pragma unroll
            for (int q = 0; q < 4; q++) acc[i][j][q] = 0.0f;

    // ---- pipeline ----
    #define LOAD_STAGE(s, c)  do {                                              \
        uint32_t db = sb + (s) * STG_BYTES;                                     \
        int k0 = (c) * KC;                                                      \
        const char* ah0 = (const char*)(g_Ah + (size_t)(m0 + r0) * K_ + k0) + c16; \
        const char* ah1 = (const char*)(g_Ah + (size_t)(m0 + r1) * K_ + k0) + c16; \
        const char* al0 = (const char*)(g_Al + (size_t)(m0 + r0) * K_ + k0) + c16; \
        const char* al1 = (const char*)(g_Al + (size_t)(m0 + r1) * K_ + k0) + c16; \
        const char* bh0 = (const char*)(g_Bh + (size_t)(n0 + r0) * K_ + k0) + c16; \
        const char* bh1 = (const char*)(g_Bh + (size_t)(n0 + r1) * K_ + k0) + c16; \
        const char* bl0 = (const char*)(g_Bl + (size_t)(n0 + r0) * K_ + k0) + c16; \
        const char* bl1 = (const char*)(g_Bl + (size_t)(n0 + r1) * K_ + k0) + c16; \
        uint32_t d0 = db + r0 * ROWB + c16;                                     \
        uint32_t d1 = db + r1 * ROWB + c16;                                     \
        CP16(d0, ah0);                      CP16(d1, ah1);                      \
        CP16(d0 + TILE_BYTES, al0);         CP16(d1 + TILE_BYTES, al1);         \
        CP16(d0 + 2 * TILE_BYTES, bh0);     CP16(d1 + 2 * TILE_BYTES, bh1);     \
        CP16(d0 + 3 * TILE_BYTES, bl0);     CP16(d1 + 3 * TILE_BYTES, bl1);     \
        asm volatile("cp.async.commit_group;" ::: "memory");                    \
    } while (0)

    LOAD_STAGE(0, 0);

    // ldmatrix lane addressing (constant across chunks)
    const int rA = wm * 64 + ((lane >> 3) & 1) * 8 + (lane & 7);
    const int cA = ((lane >> 4) & 1) * 8;                  // + kk*16
    const int rB = wn * 32 + ((lane >> 4) & 1) * 8 + (lane & 7);
    const int cB = ((lane >> 3) & 1) * 8;                  // + kk*16

    const int NCH = K_ / KC;
    for (int c = 0; c < NCH; c++) {
        if (c + 1 < NCH) {
            LOAD_STAGE((c + 1) & 1, c + 1);
            asm volatile("cp.async.wait_group 1;" ::: "memory");
        } else {
            asm volatile("cp.async.wait_group 0;" ::: "memory");
        }
        __syncthreads();

        const uint32_t st = sb + (c & 1) * STG_BYTES;
        #pragma unroll
        for (int kk = 0; kk < 2; kk++) {
            uint32_t a_h[4][4], a_l[4][4], b_h[2][4], b_l[2][4];
            #pragma unroll
            for (int mi = 0; mi < 4; mi++) {
                uint32_t ad = st + (rA + mi * 16) * ROWB + (cA + kk * 16) * 2;
                LDSM4(a_h[mi], ad);
                LDSM4(a_l[mi], ad + TILE_BYTES);
            }
            #pragma unroll
            for (int ni = 0; ni < 2; ni++) {
                uint32_t bd = st + 2 * TILE_BYTES +
                              (rB + ni * 16) * ROWB + (cB + kk * 16) * 2;
                LDSM4(b_h[ni], bd);
                LDSM4(b_l[ni], bd + TILE_BYTES);
            }
            // pass 1: Ah * Bh
            #pragma unroll
            for (int mi = 0; mi < 4; mi++)
                #pragma unroll
                for (int nj = 0; nj < 4; nj++)
                    MMA16816(acc[mi][nj], a_h[mi],
                             b_h[nj >> 1][(nj & 1) * 2], b_h[nj >> 1][(nj & 1) * 2 + 1]);
            // pass 2: Ah * Bl
            #pragma unroll
            for (int mi = 0; mi < 4; mi++)
                #pragma unroll
                for (int nj = 0; nj < 4; nj++)
                    MMA16816(acc[mi][nj], a_h[mi],
                             b_l[nj >> 1][(nj & 1) * 2], b_l[nj >> 1][(nj & 1) * 2 + 1]);
            // pass 3: Al * Bh
            #pragma unroll
            for (int mi = 0; mi < 4; mi++)
                #pragma unroll
                for (int nj = 0; nj < 4; nj++)
                    MMA16816(acc[mi][nj], a_l[mi],
                             b_h[nj >> 1][(nj & 1) * 2], b_h[nj >> 1][(nj & 1) * 2 + 1]);
        }
        __syncthreads();
    }

    // ---- epilogue: bias + store f32 ----
    #pragma unroll
    for (int mi = 0; mi < 4; mi++) {
        #pragma unroll
        for (int nj = 0; nj < 4; nj++) {
            int row = m0 + wm * 64 + mi * 16 + (lane >> 2);
            int col = n0 + wn * 32 + nj * 8 + (lane & 3) * 2;
            float2 bv = *(const float2*)(bias + col);
            float2 v0, v1;
            v0.x = acc[mi][nj][0] + bv.x;
            v0.y = acc[mi][nj][1] + bv.y;
            v1.x = acc[mi][nj][2] + bv.x;
            v1.y = acc[mi][nj][3] + bv.y;
            *(float2*)(g_qkv + (size_t)row * N_ + col)       = v0;
            *(float2*)(g_qkv + (size_t)(row + 8) * N_ + col) = v1;
        }
    }
}

// ---------------------------------------------------------------------------
// Attention kernel (unchanged; 111us measured).
// ---------------------------------------------------------------------------
__global__ __launch_bounds__(256, 4) void attn_kernel(float* __restrict__ out)
{
    __shared__ __align__(16) float qkv[3072];
    __shared__ float E[256];
    __shared__ float invden[16];

    const int token = blockIdx.x;
    const int tid   = threadIdx.x;

    const float* row = g_qkv + (size_t)token * N_;
    #pragma unroll
    for (int r = 0; r < 3; r++) {
        int i = tid + r * 256;
        ((float4*)qkv)[i] = ((const float4*)row)[i];
    }
    __syncthreads();

    const int h = tid >> 4;
    const int g = tid & 15;
    const float* qp = &qkv[h * 192];
    const float* kp = &qkv[g * 192 + 64];
    float s = 0.0f;
    #pragma unroll
    for (int dd = 0; dd < 64; dd++) {
        int d = (dd + tid) & 63;
        s = fmaf(qp[d], kp[d], s);
    }
    s -= 20.0f;
    E[tid] = (s > 20.0f || s < -20.0f) ? 0.0f : expf(s);
    __syncthreads();

    if (tid < 16) {
        float den = 0.0f;
        #pragma unroll
        for (int gg = 0; gg < 16; gg++) den += E[tid * 16 + gg];
        invden[tid] = 1.0f / den;
    }
    __syncthreads();

    float* o = out + (size_t)token * 1024;
    #pragma unroll
    for (int r = 0; r < 4; r++) {
        int idx = tid + r * 256;
        int hh = idx >> 6;
        int d  = idx & 63;
        float a = 0.0f;
        #pragma unroll
        for (int gg = 0; gg < 16; gg++)
            a = fmaf(E[hh * 16 + gg], qkv[gg * 192 + 128 + d], a);
        o[idx] = a * invden[hh];
    }
}

// ---------------------------------------------------------------------------
extern "C" void kernel_launch(void* const* d_in, const int* in_sizes, int n_in,
                              void* d_out, int out_size)
{
    const float* x = (const float*)d_in[0];
    const float* W = (const float*)d_in[1];
    const float* b = (const float*)d_in[2];
    float* out = (float*)d_out;

    cudaFuncSetAttribute(gemm_bf16_kernel,
                         cudaFuncAttributeMaxDynamicSharedMemorySize, SMEM_TOTAL);

    split_x_kernel<<<(M_ * K_) / (256 * 4), 256>>>(x);
    split_w_kernel<<<dim3(K_ / 32, N_ / 32), 256>>>(W);
    gemm_bf16_kernel<<<dim3(N_ / 128, M_ / 128), 256, SMEM_TOTAL>>>(b);
    attn_kernel<<<M_, 256>>>(out);
}

// round 5
// speedup vs baseline: 2.3862x; 1.0295x over previous
#include <cuda_runtime.h>
#include <cuda_bf16.h>
#include <cstdint>

#define M_ 16384
#define N_ 3072
#define K_ 1024

// -------- device scratch (allowed: __device__ globals) --------
__device__ float g_qkv[(size_t)M_ * N_];               // 192 MB
__device__ __nv_bfloat16 g_Ah[(size_t)M_ * K_];        // 32 MB  x hi   [M,K]
__device__ __nv_bfloat16 g_Al[(size_t)M_ * K_];        // 32 MB  x lo   [M,K]
__device__ __nv_bfloat16 g_Bh[(size_t)N_ * K_];        // 6 MB   W^T hi [N,K]
__device__ __nv_bfloat16 g_Bl[(size_t)N_ * K_];        // 6 MB   W^T lo [N,K]

// ---------------------------------------------------------------------------
// Pre-kernel 1: split x -> bf16 hi/lo, same [M,K] layout.
// ---------------------------------------------------------------------------
__global__ __launch_bounds__(256) void split_x_kernel(const float* __restrict__ x)
{
    size_t idx = (size_t)blockIdx.x * 256 + threadIdx.x;    // float4 index
    float4 v = ((const float4*)x)[idx];
    __nv_bfloat16 hx = __float2bfloat16(v.x);
    __nv_bfloat16 hy = __float2bfloat16(v.y);
    __nv_bfloat16 hz = __float2bfloat16(v.z);
    __nv_bfloat16 hw = __float2bfloat16(v.w);
    __nv_bfloat16 lx = __float2bfloat16(v.x - __bfloat162float(hx));
    __nv_bfloat16 ly = __float2bfloat16(v.y - __bfloat162float(hy));
    __nv_bfloat16 lz = __float2bfloat16(v.z - __bfloat162float(hz));
    __nv_bfloat16 lw = __float2bfloat16(v.w - __bfloat162float(hw));
    __nv_bfloat162 h01; h01.x = hx; h01.y = hy;
    __nv_bfloat162 h23; h23.x = hz; h23.y = hw;
    __nv_bfloat162 l01; l01.x = lx; l01.y = ly;
    __nv_bfloat162 l23; l23.x = lz; l23.y = lw;
    ((__nv_bfloat162*)g_Ah)[2 * idx]     = h01;
    ((__nv_bfloat162*)g_Ah)[2 * idx + 1] = h23;
    ((__nv_bfloat162*)g_Al)[2 * idx]     = l01;
    ((__nv_bfloat162*)g_Al)[2 * idx + 1] = l23;
}

// ---------------------------------------------------------------------------
// Pre-kernel 2: transpose + split W [K,N] -> g_Bh/g_Bl bf16 [N,K].
// ---------------------------------------------------------------------------
__global__ __launch_bounds__(256) void split_w_kernel(const float* __restrict__ W)
{
    __shared__ float t[32][33];
    const int k0 = blockIdx.x * 32;
    const int n0 = blockIdx.y * 32;
    const int tid = threadIdx.x;
    #pragma unroll
    for (int i = 0; i < 4; i++) {
        int idx = tid + i * 256;
        int r = idx >> 5, c = idx & 31;              // r = k local, c = n local
        t[r][c] = W[(size_t)(k0 + r) * N_ + n0 + c];
    }
    __syncthreads();
    #pragma unroll
    for (int i = 0; i < 4; i++) {
        int idx = tid + i * 256;
        int r = idx >> 5, c = idx & 31;              // r = n local, c = k local
        float v = t[c][r];
        __nv_bfloat16 hi = __float2bfloat16(v);
        __nv_bfloat16 lo = __float2bfloat16(v - __bfloat162float(hi));
        size_t o = (size_t)(n0 + r) * K_ + k0 + c;
        g_Bh[o] = hi;
        g_Bl[o] = lo;
    }
}

// ---------------------------------------------------------------------------
// Main GEMM: qkv = x @ W + b via mma.sync.m16n8k16 bf16, 3-pass split.
// CTA 128x128, 8 warps (2x4), warp tile 64x32, KC=32, cp.async double buffer.
// smem rows padded to 40 bf16 (80B) -> conflict-free ldmatrix.
// __launch_bounds__(256,2): cap regs at 128 so 2 CTAs co-reside per SM.
// ---------------------------------------------------------------------------
#define KC 32
#define ASTRIDE 40
#define ROWB (ASTRIDE * 2)                 // 80 bytes per smem row
#define TILE_BYTES (128 * ROWB)            // 10240
#define STG_BYTES (4 * TILE_BYTES)         // Ah, Al, Bh, Bl
#define SMEM_TOTAL (2 * STG_BYTES)         // 81920

__device__ __forceinline__ uint32_t cvta_smem(const void* p) {
    uint32_t a;
    asm("{ .reg .u64 t; cvta.to.shared.u64 t, %1; cvt.u32.u64 %0, t; }"
        : "=r"(a) : "l"(p));
    return a;
}

#define CP16(dst, src) \
    asm volatile("cp.async.cg.shared.global [%0], [%1], 16;" \
                 :: "r"(dst), "l"(src) : "memory")

#define LDSM4(r, addr) \
    asm volatile("ldmatrix.sync.aligned.m8n8.x4.shared.b16 {%0,%1,%2,%3}, [%4];" \
                 : "=r"((r)[0]), "=r"((r)[1]), "=r"((r)[2]), "=r"((r)[3]) \
                 : "r"(addr))

#define MMA16816(c, a, b0, b1) \
    asm volatile("mma.sync.aligned.m16n8k16.row.col.f32.bf16.bf16.f32 " \
                 "{%0,%1,%2,%3}, {%4,%5,%6,%7}, {%8,%9}, {%0,%1,%2,%3};" \
                 : "+f"((c)[0]), "+f"((c)[1]), "+f"((c)[2]), "+f"((c)[3]) \
                 : "r"((a)[0]), "r"((a)[1]), "r"((a)[2]), "r"((a)[3]), \
                   "r"(b0), "r"(b1))

__global__ __launch_bounds__(256, 2) void gemm_bf16_kernel(const float* __restrict__ bias)
{
    extern __shared__ __align__(128) char smem[];
    const uint32_t sb = cvta_smem(smem);

    const int tid  = threadIdx.x;
    const int wid  = tid >> 5;
    const int lane = tid & 31;
    const int wm   = wid >> 2;          // 0..1 (M)
    const int wn   = wid & 3;           // 0..3 (N)
    const int n0 = blockIdx.x * 128;
    const int m0 = blockIdx.y * 128;

    // per-thread cp.async coordinates: 2 x (row, 16B col) per matrix
    const int r0 = tid >> 2;            // rows 0..63
    const int r1 = r0 + 64;             // rows 64..127
    const int c16 = (tid & 3) * 16;     // byte offset within 64B row payload

    float acc[4][4][4];
    #pragma unroll
    for (int i = 0; i < 4; i++)
        #pragma unroll
        for (int j = 0; j < 4; j++)
            #pragma unroll
            for (int q = 0; q < 4; q++) acc[i][j][q] = 0.0f;

    // ---- pipeline ----
    #define LOAD_STAGE(s, c)  do {                                              \
        uint32_t db = sb + (s) * STG_BYTES;                                     \
        int k0 = (c) * KC;                                                      \
        const char* ah0 = (const char*)(g_Ah + (size_t)(m0 + r0) * K_ + k0) + c16; \
        const char* ah1 = (const char*)(g_Ah + (size_t)(m0 + r1) * K_ + k0) + c16; \
        const char* al0 = (const char*)(g_Al + (size_t)(m0 + r0) * K_ + k0) + c16; \
        const char* al1 = (const char*)(g_Al + (size_t)(m0 + r1) * K_ + k0) + c16; \
        const char* bh0 = (const char*)(g_Bh + (size_t)(n0 + r0) * K_ + k0) + c16; \
        const char* bh1 = (const char*)(g_Bh + (size_t)(n0 + r1) * K_ + k0) + c16; \
        const char* bl0 = (const char*)(g_Bl + (size_t)(n0 + r0) * K_ + k0) + c16; \
        const char* bl1 = (const char*)(g_Bl + (size_t)(n0 + r1) * K_ + k0) + c16; \
        uint32_t d0 = db + r0 * ROWB + c16;                                     \
        uint32_t d1 = db + r1 * ROWB + c16;                                     \
        CP16(d0, ah0);                      CP16(d1, ah1);                      \
        CP16(d0 + TILE_BYTES, al0);         CP16(d1 + TILE_BYTES, al1);         \
        CP16(d0 + 2 * TILE_BYTES, bh0);     CP16(d1 + 2 * TILE_BYTES, bh1);     \
        CP16(d0 + 3 * TILE_BYTES, bl0);     CP16(d1 + 3 * TILE_BYTES, bl1);     \
        asm volatile("cp.async.commit_group;" ::: "memory");                    \
    } while (0)

    LOAD_STAGE(0, 0);

    // ldmatrix lane addressing (constant across chunks)
    const int rA = wm * 64 + ((lane >> 3) & 1) * 8 + (lane & 7);
    const int cA = ((lane >> 4) & 1) * 8;                  // + kk*16
    const int rB = wn * 32 + ((lane >> 4) & 1) * 8 + (lane & 7);
    const int cB = ((lane >> 3) & 1) * 8;                  // + kk*16

    const int NCH = K_ / KC;
    for (int c = 0; c < NCH; c++) {
        if (c + 1 < NCH) {
            LOAD_STAGE((c + 1) & 1, c + 1);
            asm volatile("cp.async.wait_group 1;" ::: "memory");
        } else {
            asm volatile("cp.async.wait_group 0;" ::: "memory");
        }
        __syncthreads();

        const uint32_t st = sb + (c & 1) * STG_BYTES;
        #pragma unroll
        for (int kk = 0; kk < 2; kk++) {
            uint32_t a_h[4][4], a_l[4][4], b_h[2][4], b_l[2][4];
            #pragma unroll
            for (int mi = 0; mi < 4; mi++) {
                uint32_t ad = st + (rA + mi * 16) * ROWB + (cA + kk * 16) * 2;
                LDSM4(a_h[mi], ad);
                LDSM4(a_l[mi], ad + TILE_BYTES);
            }
            #pragma unroll
            for (int ni = 0; ni < 2; ni++) {
                uint32_t bd = st + 2 * TILE_BYTES +
                              (rB + ni * 16) * ROWB + (cB + kk * 16) * 2;
                LDSM4(b_h[ni], bd);
                LDSM4(b_l[ni], bd + TILE_BYTES);
            }
            // pass 1: Ah * Bh
            #pragma unroll
            for (int mi = 0; mi < 4; mi++)
                #pragma unroll
                for (int nj = 0; nj < 4; nj++)
                    MMA16816(acc[mi][nj], a_h[mi],
                             b_h[nj >> 1][(nj & 1) * 2], b_h[nj >> 1][(nj & 1) * 2 + 1]);
            // pass 2: Ah * Bl
            #pragma unroll
            for (int mi = 0; mi < 4; mi++)
                #pragma unroll
                for (int nj = 0; nj < 4; nj++)
                    MMA16816(acc[mi][nj], a_h[mi],
                             b_l[nj >> 1][(nj & 1) * 2], b_l[nj >> 1][(nj & 1) * 2 + 1]);
            // pass 3: Al * Bh
            #pragma unroll
            for (int mi = 0; mi < 4; mi++)
                #pragma unroll
                for (int nj = 0; nj < 4; nj++)
                    MMA16816(acc[mi][nj], a_l[mi],
                             b_h[nj >> 1][(nj & 1) * 2], b_h[nj >> 1][(nj & 1) * 2 + 1]);
        }
        __syncthreads();
    }

    // ---- epilogue: bias + store f32 ----
    #pragma unroll
    for (int mi = 0; mi < 4; mi++) {
        #pragma unroll
        for (int nj = 0; nj < 4; nj++) {
            int row = m0 + wm * 64 + mi * 16 + (lane >> 2);
            int col = n0 + wn * 32 + nj * 8 + (lane & 3) * 2;
            float2 bv = *(const float2*)(bias + col);
            float2 v0, v1;
            v0.x = acc[mi][nj][0] + bv.x;
            v0.y = acc[mi][nj][1] + bv.y;
            v1.x = acc[mi][nj][2] + bv.x;
            v1.y = acc[mi][nj][3] + bv.y;
            *(float2*)(g_qkv + (size_t)row * N_ + col)       = v0;
            *(float2*)(g_qkv + (size_t)(row + 8) * N_ + col) = v1;
        }
    }
}

// ---------------------------------------------------------------------------
// Attention kernel. Padded smem layout: head h occupies 196 floats
// (Q at h*196, K at h*196+64, V at h*196+128). 196 mod 32 = 4, so the
// 16 K-row bases spread over banks 4g mod 32 -> worst case 2-way conflict,
// and the inner dot loops are pure FFMA + induction (no skew arithmetic).
// ---------------------------------------------------------------------------
#define HSTR 196                         // padded per-head stride (floats)
#define HSTR4 49                         // float4 stride

__global__ __launch_bounds__(256, 4) void attn_kernel(float* __restrict__ out)
{
    __shared__ __align__(16) float qkv[16 * HSTR];   // 12.25 KB
    __shared__ float E[256];
    __shared__ float invden[16];

    const int token = blockIdx.x;
    const int tid   = threadIdx.x;

    // Stage token row (768 float4) into padded layout: 48 float4 per head.
    const float4* row4 = (const float4*)(g_qkv + (size_t)token * N_);
    #pragma unroll
    for (int r = 0; r < 3; r++) {
        int i = tid + r * 256;
        int head = i / 48;
        int w    = i - head * 48;
        ((float4*)qkv)[head * HSTR4 + w] = row4[i];
    }
    __syncthreads();

    // Scores: one (h,g) per thread; plain unrolled dot product.
    const int h = tid >> 4;
    const int g = tid & 15;
    const float* qp = &qkv[h * HSTR];
    const float* kp = &qkv[g * HSTR + 64];
    float s = 0.0f;
    #pragma unroll
    for (int d = 0; d < 64; d++)
        s = fmaf(qp[d], kp[d], s);
    s -= 20.0f;
    E[tid] = (s > 20.0f || s < -20.0f) ? 0.0f : expf(s);
    __syncthreads();

    if (tid < 16) {
        float den = 0.0f;
        #pragma unroll
        for (int gg = 0; gg < 16; gg++) den += E[tid * 16 + gg];
        invden[tid] = 1.0f / den;
    }
    __syncthreads();

    // out[h,d] = (1/den_h) * sum_g E[h,g] * V[g,d]
    float* o = out + (size_t)token * 1024;
    #pragma unroll
    for (int r = 0; r < 4; r++) {
        int idx = tid + r * 256;
        int hh = idx >> 6;
        int d  = idx & 63;
        float a = 0.0f;
        #pragma unroll
        for (int gg = 0; gg < 16; gg++)
            a = fmaf(E[hh * 16 + gg], qkv[gg * HSTR + 128 + d], a);
        o[idx] = a * invden[hh];
    }
}

// ---------------------------------------------------------------------------
extern "C" void kernel_launch(void* const* d_in, const int* in_sizes, int n_in,
                              void* d_out, int out_size)
{
    const float* x = (const float*)d_in[0];
    const float* W = (const float*)d_in[1];
    const float* b = (const float*)d_in[2];
    float* out = (float*)d_out;

    cudaFuncSetAttribute(gemm_bf16_kernel,
                         cudaFuncAttributeMaxDynamicSharedMemorySize, SMEM_TOTAL);

    split_x_kernel<<<(M_ * K_) / (256 * 4), 256>>>(x);
    split_w_kernel<<<dim3(K_ / 32, N_ / 32), 256>>>(W);
    gemm_bf16_kernel<<<dim3(N_ / 128, M_ / 128), 256, SMEM_TOTAL>>>(b);
    attn_kernel<<<M_, 256>>>(out);
}